// round 16
// baseline (speedup 1.0000x reference)
#include <cuda_runtime.h>
#include <cuda_fp16.h>
#include <math_constants.h>
#include <cstdint>

#define Bn 128
#define Hn 128
#define NCTA 296          // 2 CTAs/SM x 148 SMs
#define UNITS 8192        // 64 mi2 x 128 c

__device__ float    g_scores[Bn * Bn];
__device__ unsigned g_cnt = 0;
// P as swizzled fp16 tiles (128 rows x 256B, unit^(row&7) swizzle)
__device__ __align__(16) char g_Ph[128 * 32768];          // 4MB
// Per-unit row-max scratch: [unit = mi2*128+c][wn(2)][64 rows]
__device__ __align__(16) float g_rmax[UNITS * 2 * 64];    // 4MB

#define B_OFF(b)    ((b) * 32768)
#define SMEM_BYTES  (3 * 32768 + 128)

__device__ __forceinline__ uint32_t smem_u32(const void* p) {
    uint32_t a;
    asm("{ .reg .u64 t; cvta.to.shared.u64 t, %1; cvt.u32.u64 %0, t; }" : "=r"(a) : "l"(p));
    return a;
}
__device__ __forceinline__ void cp16(uint32_t sm, const void* g) {
    asm volatile("cp.async.cg.shared.global [%0], [%1], 16;" :: "r"(sm), "l"(g));
}
#define CP_COMMIT() asm volatile("cp.async.commit_group;" ::: "memory")
#define CP_WAIT(n)  asm volatile("cp.async.wait_group %0;" :: "n"(n) : "memory")

__device__ __forceinline__ void ldsm4(uint32_t& r0, uint32_t& r1, uint32_t& r2, uint32_t& r3,
                                      uint32_t addr) {
    asm volatile("ldmatrix.sync.aligned.m8n8.x4.shared.b16 {%0,%1,%2,%3}, [%4];"
                 : "=r"(r0), "=r"(r1), "=r"(r2), "=r"(r3) : "r"(addr));
}
__device__ __forceinline__ void mma16h(uint32_t* d, const uint32_t* a, uint32_t b0, uint32_t b1) {
    asm volatile(
        "mma.sync.aligned.m16n8k16.row.col.f16.f16.f16.f16 "
        "{%0,%1}, {%2,%3,%4,%5}, {%6,%7}, {%0,%1};"
        : "+r"(d[0]), "+r"(d[1])
        : "r"(a[0]), "r"(a[1]), "r"(a[2]), "r"(a[3]), "r"(b0), "r"(b1));
}
__device__ __forceinline__ uint32_t hmax2(uint32_t a, uint32_t b) {
    uint32_t r; asm("max.f16x2 %0, %1, %2;" : "=r"(r) : "r"(a), "r"(b)); return r;
}
__device__ __forceinline__ float hpair_max_f32(uint32_t p) {
    __half2 h = *reinterpret_cast<__half2*>(&p);
    return fmaxf(__half2float(__low2half(h)), __half2float(__high2half(h)));
}
__device__ __forceinline__ uint32_t pack2(float a, float b) {
    __half2 h = __floats2half2_rn(a, b);
    return *reinterpret_cast<uint32_t*>(&h);
}

// ---------------------------------------------------------------------------
// Convert (P only): fp32 [128 x 128] tile -> fp16 swizzled (row*256B,
// 16B-unit ^ (row&7)). 128 blocks x 256 threads, pure memory-bound.
// ---------------------------------------------------------------------------
extern "C" __global__ void __launch_bounds__(256)
colbert_convert(const float* __restrict__ P)
{
    const int bid = blockIdx.x, t = threadIdx.x;
    const float4* src = reinterpret_cast<const float4*>(P) + (size_t)bid * 4096;
    char* dst = g_Ph + (size_t)bid * 32768;
    #pragma unroll
    for (int j = 0; j < 16; ++j) {
        int f4 = j * 256 + t;
        float4 v = src[f4];
        int row = f4 >> 5, c4 = f4 & 31;
        uint2 w;
        w.x = pack2(v.x, v.y);
        w.y = pack2(v.z, v.w);
        int off = row * 256 + ((((c4 >> 1) ^ (row & 7))) << 4) + ((c4 & 1) << 3);
        *reinterpret_cast<uint2*>(dst + off) = w;
    }
}

// ---------------------------------------------------------------------------
// Main: 296 CTAs x 128 threads, 2 CTAs/SM over all 148 SMs.
// Work = 8192 (mi2, c) units; CTA takes a contiguous run of 27-28 units in
// <=2 mi2-segments. aF built in-kernel from raw fp32 Q (L2-resident).
// Mainloop identical to R14: f16 acc, 3-buffer cp.async ring, 1 barrier/iter.
// ---------------------------------------------------------------------------
extern "C" __global__ void __launch_bounds__(128, 2)
colbert_fused(const float* __restrict__ Q, float* __restrict__ out)
{
    extern __shared__ __align__(128) char smem[];
    const uint32_t sbase = smem_u32(smem);

    const int t    = threadIdx.x;
    const int lane = t & 31;
    const int wid  = t >> 5;
    const int wm   = wid >> 1;
    const int wn   = wid & 1;
    const int gid  = lane >> 2;
    const int tig  = lane & 3;

    const int bid = blockIdx.x;
    const int lo0 = bid * 27 + min(bid, 200);   // 8192 = 296*27 + 200
    const int hi0 = lo0 + 27 + (bid < 200 ? 1 : 0);

    const int rBl = (lane & 7) + ((lane >> 4) << 3);
    const int kqB = (lane >> 3) & 1;
    int rOff[4], rSw[4];
    #pragma unroll
    for (int np = 0; np < 4; ++np) {
        int row = wn * 64 + np * 16 + rBl;
        rOff[np] = row * 256;
        rSw[np]  = row & 7;
    }

    int lo = lo0;
    while (lo < hi0) {
        const int mi2 = lo >> 7;
        const int c0  = lo & 127;
        const int n   = min(hi0 - lo, 128 - c0);

        __syncthreads();   // prior segment's buffer reads complete

        // ---- prologue fills first (cover L2 latency with aF build below)
        {
            const char* g = g_Ph + (size_t)c0 * 32768;
            #pragma unroll
            for (int j = 0; j < 16; ++j) {
                int off = j * 2048 + t * 16;
                cp16(sbase + B_OFF(0) + off, g + off);
            }
            CP_COMMIT();
            if (n > 1) {
                const char* g1 = g + 32768;
                #pragma unroll
                for (int j = 0; j < 16; ++j) {
                    int off = j * 2048 + t * 16;
                    cp16(sbase + B_OFF(1) + off, g1 + off);
                }
            }
            CP_COMMIT();
        }

        // ---- A fragments straight from raw fp32 Q (one-time per segment)
        //      m16n8k16 A layout: lane l -> row l>>2, col 2*(l&3);
        //      a0=(r,k..k+1) a1=(r+8,k..k+1) a2=(r,k+8..k+9) a3=(r+8,k+8..k+9)
        uint32_t aF[2][8][4];
        {
            const float* Qb = Q + (size_t)(mi2 * 64 + wm * 32 + (lane >> 2)) * 128
                                + 2 * (lane & 3);
            #pragma unroll
            for (int mt = 0; mt < 2; ++mt)
                #pragma unroll
                for (int ks = 0; ks < 8; ++ks) {
                    const float* p = Qb + mt * 16 * 128 + ks * 16;
                    aF[mt][ks][0] = pack2(p[0], p[1]);
                    aF[mt][ks][1] = pack2(p[8 * 128], p[8 * 128 + 1]);
                    aF[mt][ks][2] = pack2(p[8], p[9]);
                    aF[mt][ks][3] = pack2(p[8 * 128 + 8], p[8 * 128 + 9]);
                }
        }

        for (int i = 0; i < n; ++i) {
            CP_WAIT(1);          // fill(i) complete (fill(i+1) may be pending)
            __syncthreads();     // visible to all warps; certifies iter i-1 reads done

            if (i + 2 < n) {     // refill buffer freed at iter i-1
                const char* g = g_Ph + (size_t)(c0 + i + 2) * 32768;
                const uint32_t dst = sbase + B_OFF((i + 2) % 3);
                #pragma unroll
                for (int j = 0; j < 16; ++j) {
                    int off = j * 2048 + t * 16;
                    cp16(dst + off, g + off);
                }
            }
            CP_COMMIT();         // always commit to keep group counts aligned

            const uint32_t Bbase = sbase + B_OFF(i % 3);

            uint32_t bF[2][4][4];
            #pragma unroll
            for (int np = 0; np < 4; ++np) {
                uint32_t addr = Bbase + rOff[np] + ((kqB ^ rSw[np]) << 4);
                ldsm4(bF[0][np][0], bF[0][np][1], bF[0][np][2], bF[0][np][3], addr);
            }

            uint32_t acc[2][8][2];
            #pragma unroll
            for (int mt = 0; mt < 2; ++mt)
                #pragma unroll
                for (int nt = 0; nt < 8; ++nt) { acc[mt][nt][0] = 0u; acc[mt][nt][1] = 0u; }

            #pragma unroll
            for (int ks = 0; ks < 8; ++ks) {
                const int cur = ks & 1, nxt = cur ^ 1;
                if (ks < 7) {
                    const int ku = 2 * (ks + 1) + kqB;
                    #pragma unroll
                    for (int np = 0; np < 4; ++np) {
                        uint32_t addr = Bbase + rOff[np] + ((ku ^ rSw[np]) << 4);
                        ldsm4(bF[nxt][np][0], bF[nxt][np][1], bF[nxt][np][2], bF[nxt][np][3], addr);
                    }
                }
                #pragma unroll
                for (int np = 0; np < 4; ++np)
                    #pragma unroll
                    for (int mt = 0; mt < 2; ++mt) {
                        mma16h(acc[mt][2 * np],     aF[mt][ks], bF[cur][np][0], bF[cur][np][1]);
                        mma16h(acc[mt][2 * np + 1], aF[mt][ks], bF[cur][np][2], bF[cur][np][3]);
                    }
            }

            // ---- epilogue: per-row max over this warp's 64 n-cols
            float* gr = g_rmax + ((size_t)(mi2 * 128 + c0 + i) * 2 + wn) * 64;
            #pragma unroll
            for (int mt = 0; mt < 2; ++mt) {
                uint32_t p0 = acc[mt][0][0], p1 = acc[mt][0][1];
                #pragma unroll
                for (int nt = 1; nt < 8; ++nt) {
                    p0 = hmax2(p0, acc[mt][nt][0]);
                    p1 = hmax2(p1, acc[mt][nt][1]);
                }
                float m0 = hpair_max_f32(p0);
                float m1 = hpair_max_f32(p1);
                m0 = fmaxf(m0, __shfl_xor_sync(0xffffffffu, m0, 1));
                m0 = fmaxf(m0, __shfl_xor_sync(0xffffffffu, m0, 2));
                m1 = fmaxf(m1, __shfl_xor_sync(0xffffffffu, m1, 1));
                m1 = fmaxf(m1, __shfl_xor_sync(0xffffffffu, m1, 2));
                if (tig == 0) {
                    gr[wm * 32 + mt * 16 + gid]     = m0;
                    gr[wm * 32 + mt * 16 + 8 + gid] = m1;
                }
            }
        }

        lo += n;
    }

    __syncthreads();   // all warps' g_rmax writes for this CTA visible

    // ---- combine own units: warps stride over [lo0, hi0)
    for (int u = lo0 + wid; u < hi0; u += 4) {
        const float* r = g_rmax + (size_t)u * 128;   // [wn0:64][wn1:64]
        float v0 = fmaxf(r[lane],      r[64 + lane]);
        float v1 = fmaxf(r[32 + lane], r[96 + lane]);
        #pragma unroll
        for (int off = 16; off; off >>= 1) {
            v0 += __shfl_xor_sync(0xffffffffu, v0, off);
            v1 += __shfl_xor_sync(0xffffffffu, v1, off);
        }
        if (lane == 0) {
            const int mi2u = u >> 7, c = u & 127;
            g_scores[(mi2u * 2) * Bn + c]     = v0;
            g_scores[(mi2u * 2 + 1) * Bn + c] = v1;
        }
    }

    // ---- last CTA computes the loss
    __syncthreads();
    __threadfence();
    __shared__ unsigned s_rank;
    __shared__ float sred[32];
    if (t == 0) s_rank = atomicAdd(&g_cnt, 1);
    __syncthreads();
    if (s_rank != NCTA - 1) return;
    if (t == 0) atomicExch(&g_cnt, 0);
    __threadfence();

    const float4* rp = reinterpret_cast<const float4*>(&g_scores[t * Bn]);
    float m = -CUDART_INF_F, diag = 0.0f;
    #pragma unroll
    for (int k4 = 0; k4 < 32; ++k4) {
        float4 v = rp[k4];
        m = fmaxf(m, fmaxf(fmaxf(v.x, v.y), fmaxf(v.z, v.w)));
        int cb = k4 * 4;
        if (t == cb + 0) diag = v.x;
        if (t == cb + 1) diag = v.y;
        if (t == cb + 2) diag = v.z;
        if (t == cb + 3) diag = v.w;
    }
    float s = 0.0f;
    #pragma unroll
    for (int k4 = 0; k4 < 32; ++k4) {
        float4 v = rp[k4];
        s += expf(50.0f * (v.x - m)) + expf(50.0f * (v.y - m)) +
             expf(50.0f * (v.z - m)) + expf(50.0f * (v.w - m));
    }
    float term = 50.0f * diag - (50.0f * m + logf(s));

    #pragma unroll
    for (int off = 16; off; off >>= 1) term += __shfl_xor_sync(0xffffffffu, term, off);
    if (lane == 0) sred[wid] = term;
    __syncthreads();
    if (t == 0) out[0] = -(sred[0] + sred[1] + sred[2] + sred[3]) / 128.0f;
}

// ---------------------------------------------------------------------------
extern "C" void kernel_launch(void* const* d_in, const int* in_sizes, int n_in,
                              void* d_out, int out_size)
{
    const float* Q = (const float*)d_in[0];  // [128, 32, 128]
    const float* P = (const float*)d_in[1];  // [128, 128, 128]
    float* out = (float*)d_out;

    cudaFuncSetAttribute(colbert_fused,
                         cudaFuncAttributeMaxDynamicSharedMemorySize, SMEM_BYTES);
    colbert_convert<<<128, 256>>>(P);
    colbert_fused<<<NCTA, 128, SMEM_BYTES>>>(Q, out);
}

// round 17
// speedup vs baseline: 1.0734x; 1.0734x over previous
#include <cuda_runtime.h>
#include <cuda_fp16.h>
#include <math_constants.h>
#include <cstdint>

#define Bn 128
#define Hn 128

__device__ float    g_scores[Bn * Bn];
__device__ unsigned g_cnt = 0;
// Pre-converted, pre-swizzled fp16 tiles (tile = 128 rows x 256B swizzled)
__device__ __align__(16) char g_Qh[32 * 32768];    // 1MB: 32 mi-tiles
__device__ __align__(16) char g_Ph[128 * 32768];   // 4MB: 128 c-tiles
// Deferred per-warp row-max scratch: [cta][c][wn][64]
__device__ __align__(16) float g_rmax[256 * 32 * 2 * 64];

// smem: B buf0 (32K) | B buf1 (32K) | B buf2 (32K, A overlaid during prologue)
#define B_OFF(b)   ((b) * 32768)
#define A_OFF      65536
#define SMEM_BYTES (3 * 32768 + 128)

__device__ __forceinline__ uint32_t smem_u32(const void* p) {
    uint32_t a;
    asm("{ .reg .u64 t; cvta.to.shared.u64 t, %1; cvt.u32.u64 %0, t; }" : "=r"(a) : "l"(p));
    return a;
}
__device__ __forceinline__ void cp16(uint32_t sm, const void* g) {
    asm volatile("cp.async.cg.shared.global [%0], [%1], 16;" :: "r"(sm), "l"(g));
}
#define CP_COMMIT() asm volatile("cp.async.commit_group;" ::: "memory")
#define CP_WAIT(n)  asm volatile("cp.async.wait_group %0;" :: "n"(n) : "memory")

__device__ __forceinline__ void ldsm4(uint32_t& r0, uint32_t& r1, uint32_t& r2, uint32_t& r3,
                                      uint32_t addr) {
    asm volatile("ldmatrix.sync.aligned.m8n8.x4.shared.b16 {%0,%1,%2,%3}, [%4];"
                 : "=r"(r0), "=r"(r1), "=r"(r2), "=r"(r3) : "r"(addr));
}
__device__ __forceinline__ void mma16h(uint32_t* d, const uint32_t* a, uint32_t b0, uint32_t b1) {
    asm volatile(
        "mma.sync.aligned.m16n8k16.row.col.f16.f16.f16.f16 "
        "{%0,%1}, {%2,%3,%4,%5}, {%6,%7}, {%0,%1};"
        : "+r"(d[0]), "+r"(d[1])
        : "r"(a[0]), "r"(a[1]), "r"(a[2]), "r"(a[3]), "r"(b0), "r"(b1));
}
__device__ __forceinline__ uint32_t hmax2(uint32_t a, uint32_t b) {
    uint32_t r; asm("max.f16x2 %0, %1, %2;" : "=r"(r) : "r"(a), "r"(b)); return r;
}
__device__ __forceinline__ float hpair_max_f32(uint32_t p) {
    __half2 h = *reinterpret_cast<__half2*>(&p);
    return fmaxf(__half2float(__low2half(h)), __half2float(__high2half(h)));
}
__device__ __forceinline__ uint32_t pack2(float a, float b) {
    __half2 h = __floats2half2_rn(a, b);
    return *reinterpret_cast<uint32_t*>(&h);
}

// ---------------------------------------------------------------------------
// Convert, quarter-tile granularity for max memory parallelism.
// Blocks 0..511:  P tile (bid>>2), quarter (bid&3).
// Blocks 512..639: Q tile (bid-512)>>2, quarter (bid-512)&3.
// Output layout: row*256B, 16B unit u at ((u ^ (row&7))<<4)  (R4-verified).
// ---------------------------------------------------------------------------
extern "C" __global__ void __launch_bounds__(256)
colbert_convert(const float* __restrict__ Q, const float* __restrict__ P)
{
    const int bid = blockIdx.x, t = threadIdx.x;
    const float4* src;
    char* dst;
    int qtr;
    if (bid < 512) {
        const int tile = bid >> 2; qtr = bid & 3;
        src = reinterpret_cast<const float4*>(P) + (size_t)tile * 4096;
        dst = g_Ph + (size_t)tile * 32768;
    } else {
        const int tile = (bid - 512) >> 2; qtr = (bid - 512) & 3;
        src = reinterpret_cast<const float4*>(Q) + (size_t)tile * 4096;
        dst = g_Qh + (size_t)tile * 32768;
    }
    #pragma unroll
    for (int j = 0; j < 4; ++j) {
        int f4 = qtr * 1024 + j * 256 + t;
        float4 v = src[f4];
        int row = f4 >> 5, c4 = f4 & 31;
        uint2 w;
        w.x = pack2(v.x, v.y);
        w.y = pack2(v.z, v.w);
        int off = row * 256 + ((((c4 >> 1) ^ (row & 7))) << 4) + ((c4 & 1) << 3);
        *reinterpret_cast<uint2*>(dst + off) = w;
    }
}

// ---------------------------------------------------------------------------
// Main (R11, best measured): 256 CTAs x 128 threads, 2 CTAs/SM.
// CTA (mi2=bid>>2: rows [mi2*64,+64), cg=bid&3). Warps: wm=wid>>1, wn=wid&1.
// f16 accumulators; 3-deep cp.async B pipeline; rmax deferred to global.
// ---------------------------------------------------------------------------
extern "C" __global__ void __launch_bounds__(128, 2)
colbert_fused(float* __restrict__ out)
{
    extern __shared__ __align__(128) char smem[];
    const uint32_t sbase = smem_u32(smem);

    const int t    = threadIdx.x;
    const int lane = t & 31;
    const int wid  = t >> 5;
    const int wm   = wid >> 1;
    const int wn   = wid & 1;
    const int mi2  = blockIdx.x >> 2;
    const int cg   = blockIdx.x & 3;
    const int gid  = lane >> 2;
    const int tig  = lane & 3;

    // ---- prologue
    const char* gB0 = g_Ph + (size_t)(cg * 32) * 32768;
    {
        const char* gA = g_Qh + (size_t)(mi2 >> 1) * 32768 + (size_t)(mi2 & 1) * 16384;
        #pragma unroll
        for (int j = 0; j < 8; ++j) {
            int off = j * 2048 + t * 16;
            cp16(sbase + A_OFF + off, gA + off);
        }
        #pragma unroll
        for (int j = 0; j < 16; ++j) {
            int off = j * 2048 + t * 16;
            cp16(sbase + B_OFF(0) + off, gB0 + off);
        }
        CP_COMMIT();                            // G0 = {A, tile0}
        #pragma unroll
        for (int j = 0; j < 16; ++j) {
            int off = j * 2048 + t * 16;
            cp16(sbase + B_OFF(1) + off, gB0 + 32768 + off);
        }
        CP_COMMIT();                            // G1 = {tile1}
    }
    CP_WAIT(1);
    __syncthreads();

    // ---- A fragments -> registers (from buf2 region, before tile2 lands)
    uint32_t aF[2][8][4];
    {
        const int rA = wm * 32 + (lane & 15);
        const int kqA = lane >> 4;
        #pragma unroll
        for (int mt = 0; mt < 2; ++mt) {
            const int row = rA + mt * 16;
            const uint32_t rowbase = sbase + A_OFF + row * 256;
            #pragma unroll
            for (int ks = 0; ks < 8; ++ks) {
                uint32_t addr = rowbase + (((2 * ks + kqA) ^ (row & 7)) << 4);
                ldsm4(aF[mt][ks][0], aF[mt][ks][1], aF[mt][ks][2], aF[mt][ks][3], addr);
            }
        }
    }
    __syncthreads();     // aF reads done before tile2 overwrites A region
    {
        #pragma unroll
        for (int j = 0; j < 16; ++j) {
            int off = j * 2048 + t * 16;
            cp16(sbase + B_OFF(2) + off, gB0 + 2 * 32768 + off);
        }
        CP_COMMIT();                            // G2 = {tile2}
    }

    const int rBl = (lane & 7) + ((lane >> 4) << 3);
    const int kqB = (lane >> 3) & 1;
    int rOff[4], rSw[4];
    #pragma unroll
    for (int np = 0; np < 4; ++np) {
        int row = wn * 64 + np * 16 + rBl;
        rOff[np] = row * 256;
        rSw[np]  = row & 7;
    }

    uint32_t bF[2][4][4];
    #pragma unroll
    for (int np = 0; np < 4; ++np) {
        uint32_t addr = sbase + B_OFF(0) + rOff[np] + ((kqB ^ rSw[np]) << 4);
        ldsm4(bF[0][np][0], bF[0][np][1], bF[0][np][2], bF[0][np][3], addr);
    }

    for (int i = 0; i < 32; ++i) {
        const uint32_t Bbase = sbase + B_OFF(i % 3);

        uint32_t acc[2][8][2];   // f16x2 accumulators
        #pragma unroll
        for (int mt = 0; mt < 2; ++mt)
            #pragma unroll
            for (int nt = 0; nt < 8; ++nt) { acc[mt][nt][0] = 0u; acc[mt][nt][1] = 0u; }

        #pragma unroll
        for (int ks = 0; ks < 8; ++ks) {
            const int cur = ks & 1, nxt = cur ^ 1;
            if (ks < 7) {
                const int ku = 2 * (ks + 1) + kqB;
                #pragma unroll
                for (int np = 0; np < 4; ++np) {
                    uint32_t addr = Bbase + rOff[np] + ((ku ^ rSw[np]) << 4);
                    ldsm4(bF[nxt][np][0], bF[nxt][np][1], bF[nxt][np][2], bF[nxt][np][3], addr);
                }
            }
            #pragma unroll
            for (int np = 0; np < 4; ++np)
                #pragma unroll
                for (int mt = 0; mt < 2; ++mt) {
                    mma16h(acc[mt][2 * np],     aF[mt][ks], bF[cur][np][0], bF[cur][np][1]);
                    mma16h(acc[mt][2 * np + 1], aF[mt][ks], bF[cur][np][2], bF[cur][np][3]);
                }
        }

        // ---- boundary: zero-wait recycle + next-iter bF0 prefetch
        if (i + 1 < 32) {
            if (i + 3 < 32) { CP_WAIT(1); } else { CP_WAIT(0); }
            __syncthreads();
            if (i + 3 < 32) {
                const char* gB = gB0 + (size_t)(i + 3) * 32768;
                #pragma unroll
                for (int j = 0; j < 16; ++j) {
                    int off = j * 2048 + t * 16;
                    cp16(sbase + B_OFF(i % 3) + off, gB + off);
                }
                CP_COMMIT();
            }
            const uint32_t Bnext = sbase + B_OFF((i + 1) % 3);
            #pragma unroll
            for (int np = 0; np < 4; ++np) {
                uint32_t addr = Bnext + rOff[np] + ((kqB ^ rSw[np]) << 4);
                ldsm4(bF[0][np][0], bF[0][np][1], bF[0][np][2], bF[0][np][3], addr);
            }
        }

        // ---- epilogue: packed f16 row-max over 64 n-cols -> global scratch
        float* gr = g_rmax + ((size_t)(blockIdx.x * 32 + i) * 2 + wn) * 64;
        #pragma unroll
        for (int mt = 0; mt < 2; ++mt) {
            uint32_t p0 = acc[mt][0][0], p1 = acc[mt][0][1];
            #pragma unroll
            for (int nt = 1; nt < 8; ++nt) {
                p0 = hmax2(p0, acc[mt][nt][0]);
                p1 = hmax2(p1, acc[mt][nt][1]);
            }
            float m0 = hpair_max_f32(p0);
            float m1 = hpair_max_f32(p1);
            m0 = fmaxf(m0, __shfl_xor_sync(0xffffffffu, m0, 1));
            m0 = fmaxf(m0, __shfl_xor_sync(0xffffffffu, m0, 2));
            m1 = fmaxf(m1, __shfl_xor_sync(0xffffffffu, m1, 1));
            m1 = fmaxf(m1, __shfl_xor_sync(0xffffffffu, m1, 2));
            if (tig == 0) {
                gr[wm * 32 + mt * 16 + gid]     = m0;
                gr[wm * 32 + mt * 16 + 8 + gid] = m1;
            }
        }
    }

    __syncthreads();  // all warps done; g_rmax writes visible CTA-wide

    // ---- combine: warp w handles 8 c's; lane = s-row within each b
    {
        const int b0 = mi2 * 2, b1 = mi2 * 2 + 1;
        #pragma unroll
        for (int cl = 0; cl < 8; ++cl) {
            const int ci = wid * 8 + cl;
            const float* r = g_rmax + (size_t)(blockIdx.x * 32 + ci) * 128;
            float v0 = fmaxf(r[lane],      r[64 + lane]);
            float v1 = fmaxf(r[32 + lane], r[96 + lane]);
            #pragma unroll
            for (int off = 16; off; off >>= 1) {
                v0 += __shfl_xor_sync(0xffffffffu, v0, off);
                v1 += __shfl_xor_sync(0xffffffffu, v1, off);
            }
            if (lane == 0) {
                const int c = cg * 32 + ci;
                g_scores[b0 * Bn + c] = v0;
                g_scores[b1 * Bn + c] = v1;
            }
        }
    }

    // ---- last CTA computes the loss
    __syncthreads();
    __threadfence();
    __shared__ unsigned s_rank;
    __shared__ float sred[32];
    if (t == 0) s_rank = atomicAdd(&g_cnt, 1);
    __syncthreads();
    if (s_rank != 255) return;
    if (t == 0) atomicExch(&g_cnt, 0);
    __threadfence();

    const float4* rp = reinterpret_cast<const float4*>(&g_scores[t * Bn]);
    float m = -CUDART_INF_F, diag = 0.0f;
    #pragma unroll
    for (int k4 = 0; k4 < 32; ++k4) {
        float4 v = rp[k4];
        m = fmaxf(m, fmaxf(fmaxf(v.x, v.y), fmaxf(v.z, v.w)));
        int cb = k4 * 4;
        if (t == cb + 0) diag = v.x;
        if (t == cb + 1) diag = v.y;
        if (t == cb + 2) diag = v.z;
        if (t == cb + 3) diag = v.w;
    }
    float s = 0.0f;
    #pragma unroll
    for (int k4 = 0; k4 < 32; ++k4) {
        float4 v = rp[k4];
        s += expf(50.0f * (v.x - m)) + expf(50.0f * (v.y - m)) +
             expf(50.0f * (v.z - m)) + expf(50.0f * (v.w - m));
    }
    float term = 50.0f * diag - (50.0f * m + logf(s));

    #pragma unroll
    for (int off = 16; off; off >>= 1) term += __shfl_xor_sync(0xffffffffu, term, off);
    if (lane == 0) sred[wid] = term;
    __syncthreads();
    if (t == 0) out[0] = -(sred[0] + sred[1] + sred[2] + sred[3]) / 128.0f;
}

// ---------------------------------------------------------------------------
extern "C" void kernel_launch(void* const* d_in, const int* in_sizes, int n_in,
                              void* d_out, int out_size)
{
    const float* Q = (const float*)d_in[0];  // [128, 32, 128]
    const float* P = (const float*)d_in[1];  // [128, 128, 128]
    float* out = (float*)d_out;

    cudaFuncSetAttribute(colbert_fused,
                         cudaFuncAttributeMaxDynamicSharedMemorySize, SMEM_BYTES);
    colbert_convert<<<640, 256>>>(Q, P);
    colbert_fused<<<256, 128, SMEM_BYTES>>>(out);
}